// round 5
// baseline (speedup 1.0000x reference)
#include <cuda_runtime.h>

#define Bb 4096
#define Tt 128
#define Ff 64
#define Hh 32

typedef unsigned long long u64;

// xz in gate-pair-interleaved u64 form: xzp[row][p] with
//   p in [0,32):  (z_i[p],    z_f[p])      (gates p, p+32)
//   p in [32,64): (z_g[p-32], z_o[p-32])   (gates 64+q, 96+q)
__device__ u64 g_xzp[(size_t)Bb * Tt * 64];

// ---------- f32x2 packed helpers ----------
__device__ __forceinline__ u64 pk2(float lo, float hi) {
    u64 r; asm("mov.b64 %0, {%1, %2};" : "=l"(r) : "f"(lo), "f"(hi)); return r;
}
__device__ __forceinline__ void upk2(u64 v, float &lo, float &hi) {
    asm("mov.b64 {%0, %1}, %2;" : "=f"(lo), "=f"(hi) : "l"(v));
}
__device__ __forceinline__ u64 fma2(u64 a, u64 b, u64 c) {
    u64 d; asm("fma.rn.f32x2 %0, %1, %2, %3;" : "=l"(d) : "l"(a), "l"(b), "l"(c)); return d;
}
__device__ __forceinline__ u64 add2(u64 a, u64 b) {
    u64 d; asm("add.rn.f32x2 %0, %1, %2;" : "=l"(d) : "l"(a), "l"(b)); return d;
}

__device__ __forceinline__ float sigf(float x) {
    return __fdividef(1.0f, 1.0f + __expf(-x));
}
__device__ __forceinline__ float cellf(float zi, float zf, float zg, float zo, float &c) {
    float i = sigf(zi);
    float f = sigf(zf);
    float g = fmaxf(zg, 0.0f);
    float o = sigf(zo);
    c = fmaf(f, c, i * g);
    return o * fmaxf(c, 0.0f);
}

// =====================================================================
// Kernel 1: xz = x @ We + be, output in gate-pair-interleaved u64 layout.
// 4096 CTAs x 128 rows, 256 threads, 2 CTAs/SM (16 warps/SM).
// Thread tile: 8 rows x 4 gate-pairs. Pair p owned by (tx,j) = j*16+tx.
// =====================================================================
__global__ __launch_bounds__(256, 2) void k_xz(const float* __restrict__ x,
                                               const float* __restrict__ We,
                                               const float* __restrict__ be)
{
    __shared__ __align__(16) u64   wsp[64 * 64];   // 32 KB: (We[k][g], We[k][g+32]) pairs
    __shared__ __align__(16) float xs[128 * 64];   // 32 KB
    const int tid = threadIdx.x;

    // pack We into gate pairs
    for (int i = tid; i < 64 * 64; i += 256) {
        int k = i >> 6, p = i & 63;
        int base = (p & 32) ? 64 : 0;
        int q = p & 31;
        const float* w = We + k * 128 + base + q;
        wsp[i] = pk2(__ldg(w), __ldg(w + 32));
    }
    const float4* xsrc = (const float4*)(x + (size_t)blockIdx.x * 128 * 64);
    for (int i = tid; i < 128 * 16; i += 256) {
        *(float4*)(xs + i * 4) = __ldg(xsrc + i);
    }
    __syncthreads();

    const int tx = tid & 15, ty = tid >> 4;

    u64 acc[8][4];
#pragma unroll
    for (int r = 0; r < 8; r++)
#pragma unroll
        for (int j = 0; j < 4; j++) acc[r][j] = 0ULL;

    const float* xr = xs + ty * 8 * 64;

#pragma unroll 2
    for (int kq = 0; kq < 16; kq++) {
        float4 xv[8];
#pragma unroll
        for (int r = 0; r < 8; r++) xv[r] = *(const float4*)(xr + r * 64 + kq * 4);
#pragma unroll
        for (int kk = 0; kk < 4; kk++) {
            int k = kq * 4 + kk;
            u64 b[4];
#pragma unroll
            for (int j = 0; j < 4; j++) b[j] = wsp[k * 64 + j * 16 + tx];
#pragma unroll
            for (int r = 0; r < 8; r++) {
                float a = (&xv[r].x)[kk];
                u64 a2 = pk2(a, a);
#pragma unroll
                for (int j = 0; j < 4; j++) acc[r][j] = fma2(a2, b[j], acc[r][j]);
            }
        }
    }

    u64 be2[4];
#pragma unroll
    for (int j = 0; j < 4; j++) {
        int p = j * 16 + tx;
        int base = (p & 32) ? 64 : 0;
        int q = p & 31;
        be2[j] = pk2(__ldg(be + base + q), __ldg(be + base + 32 + q));
    }

#pragma unroll
    for (int r = 0; r < 8; r++) {
        size_t row = (size_t)blockIdx.x * 128 + ty * 8 + r;
#pragma unroll
        for (int j = 0; j < 4; j++)
            g_xzp[row * 64 + j * 16 + tx] = add2(acc[r][j], be2[j]);
    }
}

// =====================================================================
// Kernel 2: fused encoder + decoder + Dense(64).
// Warp = 2 batch rows, lane = hidden unit. U in registers (reloaded
// between phases). h broadcast via pre-duplicated u64 in warp-private
// smem (double-buffered, one __syncwarp per step). 512 CTAs x 128 thr.
// =====================================================================
__global__ __launch_bounds__(128, 2) void k_rnn(const float* __restrict__ Ue,
                                                const float* __restrict__ Ud,
                                                const float* __restrict__ Wd,
                                                const float* __restrict__ bd,
                                                const float* __restrict__ Wout,
                                                const float* __restrict__ bout,
                                                float* __restrict__ y)
{
    __shared__ __align__(16) u64 Wos[32 * 32];    // 8KB: (Wout[kk][l], Wout[kk][32+l])
    __shared__ __align__(16) u64 hds[4 * 128];    // 4KB: [warp][buf(2)][row(2)][32]
    const int tid = threadIdx.x;
    const int lane = tid & 31;
    const int wid = tid >> 5;
    const int gwarp = blockIdx.x * 4 + wid;
    const int row0 = gwarp * 2;

    for (int i = tid; i < 32 * 32; i += 128) {
        int kk = i >> 5, l = i & 31;
        Wos[i] = pk2(__ldg(Wout + kk * 64 + l), __ldg(Wout + kk * 64 + 32 + l));
    }
    __syncthreads();

    u64* hd = hds + wid * 128;   // [buf*64 + row*32 + kk]

    // ---------------- encoder ----------------
    u64 wif[32], wgo[32];
#pragma unroll
    for (int kk = 0; kk < 32; kk++) {
        const float* u = Ue + kk * 128;
        wif[kk] = pk2(__ldg(u + lane),      __ldg(u + 32 + lane));
        wgo[kk] = pk2(__ldg(u + 64 + lane), __ldg(u + 96 + lane));
    }

    // zero both h buffers
    hd[lane] = 0ULL; hd[32 + lane] = 0ULL; hd[64 + lane] = 0ULL; hd[96 + lane] = 0ULL;
    __syncwarp();

    const u64* xzr0 = g_xzp + (size_t)row0 * 128 * 64;
    const u64* xzr1 = xzr0 + 128 * 64;

    float h0 = 0.f, h1 = 0.f, cc0 = 0.f, cc1 = 0.f;

    u64 nif0 = __ldg(xzr0 + lane), ngo0 = __ldg(xzr0 + 32 + lane);
    u64 nif1 = __ldg(xzr1 + lane), ngo1 = __ldg(xzr1 + 32 + lane);

    for (int t = 0; t < 128; t++) {
        const u64* hc = hd + (t & 1) * 64;
        u64 aif0 = nif0, ago0 = ngo0, aif1 = nif1, ago1 = ngo1;

        if (t < 127) {
            const u64* p0 = xzr0 + (size_t)(t + 1) * 64;
            const u64* p1 = xzr1 + (size_t)(t + 1) * 64;
            nif0 = __ldg(p0 + lane); ngo0 = __ldg(p0 + 32 + lane);
            nif1 = __ldg(p1 + lane); ngo1 = __ldg(p1 + 32 + lane);
        }

#pragma unroll
        for (int kk = 0; kk < 32; kk++) {
            u64 h0d = hc[kk];
            u64 h1d = hc[32 + kk];
            aif0 = fma2(h0d, wif[kk], aif0);
            ago0 = fma2(h0d, wgo[kk], ago0);
            aif1 = fma2(h1d, wif[kk], aif1);
            ago1 = fma2(h1d, wgo[kk], ago1);
        }

        float zi, zf, zg, zo;
        upk2(aif0, zi, zf); upk2(ago0, zg, zo);
        h0 = cellf(zi, zf, zg, zo, cc0);
        upk2(aif1, zi, zf); upk2(ago1, zg, zo);
        h1 = cellf(zi, zf, zg, zo, cc1);

        u64* hn = hd + ((t & 1) ^ 1) * 64;
        hn[lane] = pk2(h0, h0);
        hn[32 + lane] = pk2(h1, h1);
        __syncwarp();
    }

    // ---------------- zd = hT @ Wd + bd (once) ----------------
    float ht0 = h0, ht1 = h1;
    u64 zif0 = pk2(__ldg(bd + lane),      __ldg(bd + 32 + lane));
    u64 zgo0 = pk2(__ldg(bd + 64 + lane), __ldg(bd + 96 + lane));
    u64 zif1 = zif0, zgo1 = zgo0;
#pragma unroll
    for (int kk = 0; kk < 32; kk++) {
        float hv0 = __shfl_sync(0xffffffffu, ht0, kk);
        float hv1 = __shfl_sync(0xffffffffu, ht1, kk);
        const float* w = Wd + kk * 128;
        u64 vif = pk2(__ldg(w + lane),      __ldg(w + 32 + lane));
        u64 vgo = pk2(__ldg(w + 64 + lane), __ldg(w + 96 + lane));
        u64 hp0 = pk2(hv0, hv0);
        u64 hp1 = pk2(hv1, hv1);
        zif0 = fma2(hp0, vif, zif0);
        zgo0 = fma2(hp0, vgo, zgo0);
        zif1 = fma2(hp1, vif, zif1);
        zgo1 = fma2(hp1, vgo, zgo1);
    }

    // ---------------- decoder (reload U = Ud) ----------------
#pragma unroll
    for (int kk = 0; kk < 32; kk++) {
        const float* u = Ud + kk * 128;
        wif[kk] = pk2(__ldg(u + lane),      __ldg(u + 32 + lane));
        wgo[kk] = pk2(__ldg(u + 64 + lane), __ldg(u + 96 + lane));
    }

    hd[lane] = 0ULL; hd[32 + lane] = 0ULL; hd[64 + lane] = 0ULL; hd[96 + lane] = 0ULL;
    __syncwarp();

    h0 = 0.f; h1 = 0.f; cc0 = 0.f; cc1 = 0.f;
    u64 bo = pk2(__ldg(bout + lane), __ldg(bout + 32 + lane));
    float* y0 = y + (size_t)row0 * 128 * 64;
    float* y1 = y0 + 128 * 64;

    for (int t = 0; t < 128; t++) {
        const u64* hc = hd + (t & 1) * 64;
        u64 aif0 = zif0, ago0 = zgo0, aif1 = zif1, ago1 = zgo1;
        u64 ya0 = bo, ya1 = bo;

#pragma unroll
        for (int kk = 0; kk < 32; kk++) {
            u64 h0d = hc[kk];
            u64 h1d = hc[32 + kk];
            aif0 = fma2(h0d, wif[kk], aif0);
            ago0 = fma2(h0d, wgo[kk], ago0);
            aif1 = fma2(h1d, wif[kk], aif1);
            ago1 = fma2(h1d, wgo[kk], ago1);
            u64 wo = Wos[kk * 32 + lane];
            ya0 = fma2(h0d, wo, ya0);
            ya1 = fma2(h1d, wo, ya1);
        }

        if (t > 0) {   // ya used h_t = hs[t-1] -> y[t-1]
            float a, b;
            upk2(ya0, a, b);
            y0[(size_t)(t - 1) * 64 + lane] = a;
            y0[(size_t)(t - 1) * 64 + 32 + lane] = b;
            upk2(ya1, a, b);
            y1[(size_t)(t - 1) * 64 + lane] = a;
            y1[(size_t)(t - 1) * 64 + 32 + lane] = b;
        }

        float zi, zf, zg, zo;
        upk2(aif0, zi, zf); upk2(ago0, zg, zo);
        h0 = cellf(zi, zf, zg, zo, cc0);
        upk2(aif1, zi, zf); upk2(ago1, zg, zo);
        h1 = cellf(zi, zf, zg, zo, cc1);

        u64* hn = hd + ((t & 1) ^ 1) * 64;
        hn[lane] = pk2(h0, h0);
        hn[32 + lane] = pk2(h1, h1);
        __syncwarp();
    }

    // epilogue: y[127] from h_128 (in hd buf 0 after t=127)
    {
        const u64* hc = hd;   // buf 0
        u64 ya0 = bo, ya1 = bo;
#pragma unroll
        for (int kk = 0; kk < 32; kk++) {
            u64 wo = Wos[kk * 32 + lane];
            ya0 = fma2(hc[kk], wo, ya0);
            ya1 = fma2(hc[32 + kk], wo, ya1);
        }
        float a, b;
        upk2(ya0, a, b);
        y0[(size_t)127 * 64 + lane] = a;
        y0[(size_t)127 * 64 + 32 + lane] = b;
        upk2(ya1, a, b);
        y1[(size_t)127 * 64 + lane] = a;
        y1[(size_t)127 * 64 + 32 + lane] = b;
    }
}

// =====================================================================
extern "C" void kernel_launch(void* const* d_in, const int* in_sizes, int n_in,
                              void* d_out, int out_size)
{
    const float* x    = (const float*)d_in[0];
    const float* We   = (const float*)d_in[1];
    const float* Ue   = (const float*)d_in[2];
    const float* be   = (const float*)d_in[3];
    const float* Wd   = (const float*)d_in[4];
    const float* Ud   = (const float*)d_in[5];
    const float* bd   = (const float*)d_in[6];
    const float* Wout = (const float*)d_in[7];
    const float* bout = (const float*)d_in[8];
    float* y = (float*)d_out;

    k_xz<<<4096, 256>>>(x, We, be);
    k_rnn<<<512, 128>>>(Ue, Ud, Wd, bd, Wout, bout, y);
}